// round 11
// baseline (speedup 1.0000x reference)
#include <cuda_runtime.h>
#include <cuda_bf16.h>
#include <math.h>
#include <stdint.h>

typedef unsigned long long ull;

// ===================== helpers =====================
__device__ __forceinline__ uint32_t smem_u32(const void* p) {
    uint32_t a;
    asm("{ .reg .u64 t; cvta.to.shared.u64 t, %1; cvt.u32.u64 %0, t; }" : "=r"(a) : "l"(p));
    return a;
}

#define LOG2E 1.4426950408889634f
__device__ __forceinline__ float ex2f(float x) { float r; asm("ex2.approx.ftz.f32 %0, %1;" : "=f"(r) : "f"(x)); return r; }
__device__ __forceinline__ float tanhx(float x) { float r; asm("tanh.approx.f32 %0, %1;" : "=f"(r) : "f"(x)); return r; }
__device__ __forceinline__ float sigx(float x)  { return fmaf(tanhx(0.5f * x), 0.5f, 0.5f); }

// mma.sync m16n8k16 bf16 (sm_80+, no arch suffix)
__device__ __forceinline__ void mma16816(float* c, const uint32_t* a, const uint32_t* b) {
    asm volatile(
        "mma.sync.aligned.m16n8k16.row.col.f32.bf16.bf16.f32 "
        "{%0,%1,%2,%3}, {%4,%5,%6,%7}, {%8,%9}, {%0,%1,%2,%3};"
        : "+f"(c[0]), "+f"(c[1]), "+f"(c[2]), "+f"(c[3])
        : "r"(a[0]), "r"(a[1]), "r"(a[2]), "r"(a[3]), "r"(b[0]), "r"(b[1]));
}
#define LDSM4(r, a) \
    asm volatile("ldmatrix.sync.aligned.m8n8.x4.shared.b16 {%0,%1,%2,%3}, [%4];" \
        : "=r"((r)[0]), "=r"((r)[1]), "=r"((r)[2]), "=r"((r)[3]) : "r"(a))
#define LDSM2(r, a) \
    asm volatile("ldmatrix.sync.aligned.m8n8.x2.shared.b16 {%0,%1}, [%2];" \
        : "=r"((r)[0]), "=r"((r)[1]) : "r"(a))

#define CP16(dst, src) \
    asm volatile("cp.async.cg.shared.global [%0], [%1], 16;" :: "r"(dst), "l"(src) : "memory")
#define CP_COMMIT() asm volatile("cp.async.commit_group;" ::: "memory")
#define CP_WAIT1()  asm volatile("cp.async.wait_group 1;" ::: "memory")
#define CP_WAIT0()  asm volatile("cp.async.wait_group 0;" ::: "memory")

// ===================== global scratch =====================
// packed weights: [matgate 6][plane hi/lo][n 192][k 192] bf16 (hi plane staged)
__device__ __nv_bfloat16 g_Wpk[6 * 2 * 192 * 192];
__device__ float g_bias[6 * 192];            // [matgate][n], zero-padded
__device__ __nv_bfloat16 g_hdec[88473600];   // [2048][240][180] bf16
__device__ float g_part[16 * 2048 * 40];

// ===================== smem layout (bytes) =====================
// A: 2 planes x [48 rows][200 bf16] (400B rows)
#define OA    0
#define APL   19200
// B: 3 slots x [192 n][40 bf16] (80B rows = 32 k + pad), hi plane only
#define OB    38400
#define BSLOT 15360
// C: bf16 [192 n][56 t]
#define OC    84480
// red: redM[192], redS[192]
#define ORED  105984
#define SMEM_TOT 107520

// ===================== prep: pack weights (bf16 hi/lo planes) + bias =====================
__global__ void prep_weights(const float* __restrict__ We, const float* __restrict__ bie,
                             const float* __restrict__ bhe, const float* __restrict__ Wd,
                             const float* __restrict__ bid, const float* __restrict__ bhd) {
    const int gb[3] = {0, 360, 540};   // torch gates i,f,g,o -> keep i,g,o (f dead: c_prev=0)
    int idx = blockIdx.x * blockDim.x + threadIdx.x;
    int stride = gridDim.x * blockDim.x;
    for (int i = idx; i < 6 * 192 * 192; i += stride) {
        int k = i % 192, n = (i / 192) % 192, g = (i / 36864) % 3, mat = i / 110592;
        float v = 0.f;
        if (n < 180 && k < 180) v = (mat ? Wd : We)[(gb[g] + n) * 180 + k];
        __nv_bfloat16 h = __float2bfloat16(v);
        __nv_bfloat16 l = __float2bfloat16(v - __bfloat162float(h));
        size_t base = (size_t)(mat * 3 + g) * 2 * 36864 + (size_t)n * 192 + k;
        g_Wpk[base] = h;
        g_Wpk[base + 36864] = l;
    }
    for (int i = idx; i < 6 * 192; i += stride) {
        int n = i % 192, g = (i / 192) % 3, mat = i / 576;
        float v = 0.f;
        if (n < 180) v = (mat ? bid : bie)[gb[g] + n] + (mat ? bhd : bhe)[gb[g] + n];
        g_bias[(mat * 3 + g) * 192 + n] = v;
    }
}

// dummies: shift fused_encdec to in-call launch position 4 so ncu samples it
__global__ void dummy_k() {}

// ===================== B chunk staging (k32, hi plane, 3 slots) =====================
__device__ __forceinline__ void stage_chunk(uint32_t sb, int tid, int c) {
    int mg = c / 6, kc = c % 6;              // matgate 0..5, k-chunk 0..5
    const char* base = (const char*)g_Wpk + (size_t)mg * 147456;   // plane 0 = hi
    uint32_t dstb = sb + OB + (uint32_t)(c % 3) * BSLOT;
#pragma unroll
    for (int it = 0; it < 3; it++) {
        int idx = tid + it * 256;            // 0..767
        int j = idx & 3;                     // 16B piece within 64B row chunk
        int n = idx >> 2;                    // 0..191
        const void* src = base + (size_t)n * 384 + kc * 64 + j * 16;
        uint32_t dst = dstb + (uint32_t)n * 80 + (uint32_t)j * 16;
        CP16(dst, src);
    }
}

// ===================== fused enc -> softmax -> dec =====================
__global__ void __launch_bounds__(256, 2) fused_encdec(const float* __restrict__ x) {
    extern __shared__ char sm[];
    const uint32_t sb = smem_u32(sm);
    __nv_bfloat16* C = (__nv_bfloat16*)(sm + OC);
    float* redM = (float*)(sm + ORED);
    float* redS = redM + 192;
    const int tid = threadIdx.x, lane = tid & 31, wid = tid >> 5;
    const int b = blockIdx.y, t0 = blockIdx.x * 48;

    // Build A planes from x[b][k][t0+t]
    for (int i = tid; i < 192 * 48; i += 256) {
        int k = i / 48, t = i % 48;
        float v = (k < 180) ? x[((size_t)b * 180 + k) * 240 + t0 + t] : 0.f;
        __nv_bfloat16 h = __float2bfloat16(v);
        __nv_bfloat16 l = __float2bfloat16(v - __bfloat162float(h));
        *(__nv_bfloat16*)(sm + OA + t * 400 + k * 2) = h;
        *(__nv_bfloat16*)(sm + OA + APL + t * 400 + k * 2) = l;
    }

    // ldmatrix per-lane offsets
    const int rit = lane & 7, grp = lane >> 3;
    const uint32_t aoff = (uint32_t)((rit + (grp & 1) * 8) * 400 + (grp >> 1) * 16);
    const int l2 = lane & 15;
    const uint32_t boff = (uint32_t)((l2 & 7) * 80 + (l2 >> 3) * 16);

    stage_chunk(sb, tid, 0);
    CP_COMMIT();

    int c = 0;
    float sval[36];
    for (int mat = 0; mat < 2; mat++) {
        for (int g = 0; g < 3; g++) {
            float acc[36];
#pragma unroll
            for (int v = 0; v < 36; v++) acc[v] = 0.f;

            for (int kc = 0; kc < 6; kc++, c++) {
                // single-sync 3-slot pipeline:
                // stage c+1 (slot (c+1)%3) is safe: laggards are at most in chunk c-1
                // (slot (c-1)%3) — distinct mod 3.
                if (c + 1 < 36) { stage_chunk(sb, tid, c + 1); CP_COMMIT(); CP_WAIT1(); }
                else CP_WAIT0();
                __syncthreads();   // chunk c visible; orders A-plane writes too
                uint32_t Bbase = sb + OB + (uint32_t)(c % 3) * BSLOT;
#pragma unroll
                for (int s = 0; s < 2; s++) {
                    const int k0 = kc * 32 + s * 16;       // global k for A
                    uint32_t Ah[3][4], Al[3][4];
#pragma unroll
                    for (int mi = 0; mi < 3; mi++) {
                        uint32_t a = sb + OA + (uint32_t)(mi * 6400) + (uint32_t)(k0 * 2) + aoff;
                        LDSM4(Ah[mi], a);
                        LDSM4(Al[mi], a + APL);
                    }
                    uint32_t Bh[3][2];
#pragma unroll
                    for (int ni = 0; ni < 3; ni++) {
                        uint32_t ba = Bbase + (uint32_t)((wid * 24 + ni * 8) * 80) +
                                      (uint32_t)(s * 32) + boff;
                        LDSM2(Bh[ni], ba);
                    }
#pragma unroll
                    for (int mi = 0; mi < 3; mi++)
#pragma unroll
                        for (int ni = 0; ni < 3; ni++) {
                            float* cc = &acc[(mi * 3 + ni) * 4];
                            mma16816(cc, Ah[mi], Bh[ni]);   // hi*hi
                            mma16816(cc, Al[mi], Bh[ni]);   // lo*hi
                        }
                }
            }

            // ---- gate epilogue (thread<->element mapping identical across gates) ----
            const float* bias = g_bias + (mat * 3 + g) * 192;
#pragma unroll
            for (int mi = 0; mi < 3; mi++)
#pragma unroll
                for (int ni = 0; ni < 3; ni++) {
                    int nb = wid * 24 + ni * 8 + (lane & 3) * 2;
                    float b0 = __ldg(bias + nb), b1 = __ldg(bias + nb + 1);
#pragma unroll
                    for (int r = 0; r < 4; r++) {
                        int v = (mi * 3 + ni) * 4 + r;
                        float bb = (r & 1) ? b1 : b0;
                        if (g == 0) {
                            sval[v] = sigx(acc[v] + bb);                        // sig(i)
                        } else if (g == 1) {
                            sval[v] = tanhx(sval[v] * tanhx(acc[v] + bb));      // tanh(c)
                        } else {
                            int t = mi * 16 + (lane >> 2) + ((r >> 1) & 1) * 8;
                            int n = nb + (r & 1);
                            C[n * 56 + t] = __float2bfloat16(sigx(acc[v] + bb) * sval[v]); // h
                        }
                    }
                }

            if (g == 2) {
                __syncthreads();   // C complete
                if (mat == 0) {
                    // softmax over n per t; rewrite A planes with decoder input
                    int t = tid >> 2, sl = tid & 3, n0 = sl * 45, n1 = n0 + 45;
                    if (tid < 192) {
                        float m = -1e30f;
                        for (int n = n0; n < n1; n++) m = fmaxf(m, __bfloat162float(C[n * 56 + t]));
                        redM[sl * 48 + t] = m;
                    }
                    __syncthreads();
                    if (tid < 192) {
                        float mm = fmaxf(fmaxf(redM[t], redM[48 + t]),
                                         fmaxf(redM[96 + t], redM[144 + t]));
                        float s = 0.f;
                        for (int n = n0; n < n1; n++) {
                            float e = ex2f((__bfloat162float(C[n * 56 + t]) - mm) * LOG2E);
                            C[n * 56 + t] = __float2bfloat16(e);
                            s += e;
                        }
                        redS[sl * 48 + t] = s;
                    }
                    __syncthreads();
                    if (tid < 192) {
                        float inv = 1.f / (redS[t] + redS[48 + t] + redS[96 + t] + redS[144 + t]);
                        for (int n = n0; n < n1; n++) {
                            float v = __bfloat162float(C[n * 56 + t]) * inv;
                            __nv_bfloat16 h = __float2bfloat16(v);
                            __nv_bfloat16 l = __float2bfloat16(v - __bfloat162float(h));
                            *(__nv_bfloat16*)(sm + OA + t * 400 + n * 2) = h;
                            *(__nv_bfloat16*)(sm + OA + APL + t * 400 + n * 2) = l;
                        }
                    }
                    // next chunk's sync orders these A writes vs ldmatrix
                } else {
                    for (int i = tid; i < 48 * 180; i += 256) {
                        int t = i / 180, n = i % 180;
                        g_hdec[((size_t)b * 240 + t0 + t) * 180 + n] = C[n * 56 + t];
                    }
                }
            }
        }
    }
}

// ---------------- output GEMM, split-K partials (bf16 h loads) ----------------
__device__ __forceinline__ ull ffma2(ull a, ull b, ull c) {
    ull d;
    asm("fma.rn.f32x2 %0, %1, %2, %3;" : "=l"(d) : "l"(a), "l"(b), "l"(c));
    return d;
}
__device__ __forceinline__ float2 unpackf2(ull v) {
    float2 r;
    asm("mov.b64 {%0, %1}, %2;" : "=f"(r.x), "=f"(r.y) : "l"(v));
    return r;
}

__global__ void __launch_bounds__(256) out_gemm(const float* __restrict__ Wout) {
    __shared__ float Hc[64][62];
    __shared__ float Wc[40][62];
    const int ks = blockIdx.x;
    const int b0 = blockIdx.y * 64;
    const int k0 = ks * 2700;
    const int tid = threadIdx.x;
    const int bg = tid % 32;
    const int ng = tid / 32;

    ull acc2[2][5];
#pragma unroll
    for (int bi = 0; bi < 2; bi++)
#pragma unroll
        for (int q = 0; q < 5; q++) acc2[bi][q] = 0ull;

    for (int cc = 0; cc < 45; cc++) {
        __syncthreads();
        const int kb = k0 + cc * 60;
        for (int i = tid; i < 64 * 30; i += 256) {
            int bb = i / 30, k2 = i % 30;
            __nv_bfloat162 p = *(const __nv_bfloat162*)&g_hdec[(size_t)(b0 + bb) * 43200 + kb + k2 * 2];
            Hc[bb][k2 * 2]     = __bfloat162float(p.x);
            Hc[bb][k2 * 2 + 1] = __bfloat162float(p.y);
        }
        for (int i = tid; i < 40 * 60; i += 256) {
            int n = i / 60, k = i % 60;
            Wc[n][k] = Wout[(size_t)n * 43200 + kb + k];
        }
        __syncthreads();
#pragma unroll 6
        for (int kp = 0; kp < 30; kp++) {
            ull h0 = *(const ull*)&Hc[bg][kp * 2];
            ull h1 = *(const ull*)&Hc[bg + 32][kp * 2];
#pragma unroll
            for (int q = 0; q < 5; q++) {
                ull w = *(const ull*)&Wc[ng * 5 + q][kp * 2];
                acc2[0][q] = ffma2(h0, w, acc2[0][q]);
                acc2[1][q] = ffma2(h1, w, acc2[1][q]);
            }
        }
    }
#pragma unroll
    for (int bi = 0; bi < 2; bi++)
#pragma unroll
        for (int q = 0; q < 5; q++) {
            float2 p = unpackf2(acc2[bi][q]);
            g_part[((size_t)ks * 2048 + b0 + bg + 32 * bi) * 40 + ng * 5 + q] = p.x + p.y;
        }
}

__global__ void reduce_softmax(const float* __restrict__ bout, float* __restrict__ out) {
    __shared__ float smv[40];
    const int b = blockIdx.x;
    const int n = threadIdx.x;
    float l = bout[n];
#pragma unroll
    for (int ks = 0; ks < 16; ks++) l += g_part[((size_t)ks * 2048 + b) * 40 + n];
    smv[n] = l;
    __syncthreads();
    const int g0 = (n / 10) * 10;
    float m = smv[g0];
#pragma unroll
    for (int i = 1; i < 10; i++) m = fmaxf(m, smv[g0 + i]);
    float s = 0.f;
#pragma unroll
    for (int i = 0; i < 10; i++) s += expf(smv[g0 + i] - m);
    out[(size_t)b * 40 + n] = expf(l - m) / s;
}

// ---------------- launcher ----------------
extern "C" void kernel_launch(void* const* d_in, const int* in_sizes, int n_in,
                              void* d_out, int out_size) {
    const float* x    = (const float*)d_in[0];
    const float* Wenc = (const float*)d_in[1];
    const float* bie  = (const float*)d_in[2];
    const float* bhe  = (const float*)d_in[3];
    const float* Wdec = (const float*)d_in[4];
    const float* bid  = (const float*)d_in[5];
    const float* bhd  = (const float*)d_in[6];
    const float* Wout = (const float*)d_in[7];
    const float* bout = (const float*)d_in[8];
    float* out = (float*)d_out;

    cudaFuncSetAttribute(fused_encdec, cudaFuncAttributeMaxDynamicSharedMemorySize, SMEM_TOT);

    prep_weights<<<256, 256>>>(Wenc, bie, bhe, Wdec, bid, bhd);
    dummy_k<<<1, 32>>>();
    dummy_k<<<1, 32>>>();   // fused_encdec is now in-call launch #4 (ncu steering)
    fused_encdec<<<dim3(5, 2048), 256, SMEM_TOT>>>(x);
    out_gemm<<<dim3(16, 32), 256>>>(Wout);
    reduce_softmax<<<2048, 40>>>(bout, out);
}

// round 12
// speedup vs baseline: 1.4310x; 1.4310x over previous
#include <cuda_runtime.h>
#include <cuda_bf16.h>
#include <math.h>
#include <stdint.h>

typedef unsigned long long ull;

// ===================== helpers =====================
__device__ __forceinline__ uint32_t smem_u32(const void* p) {
    uint32_t a;
    asm("{ .reg .u64 t; cvta.to.shared.u64 t, %1; cvt.u32.u64 %0, t; }" : "=r"(a) : "l"(p));
    return a;
}

#define LOG2E 1.4426950408889634f
__device__ __forceinline__ float ex2f(float x) { float r; asm("ex2.approx.ftz.f32 %0, %1;" : "=f"(r) : "f"(x)); return r; }
__device__ __forceinline__ float tanhx(float x) { float r; asm("tanh.approx.f32 %0, %1;" : "=f"(r) : "f"(x)); return r; }
__device__ __forceinline__ float sigx(float x)  { return fmaf(tanhx(0.5f * x), 0.5f, 0.5f); }

// mma.sync m16n8k16 bf16 (sm_80+, no arch suffix)
__device__ __forceinline__ void mma16816(float* c, const uint32_t* a, const uint32_t* b) {
    asm volatile(
        "mma.sync.aligned.m16n8k16.row.col.f32.bf16.bf16.f32 "
        "{%0,%1,%2,%3}, {%4,%5,%6,%7}, {%8,%9}, {%0,%1,%2,%3};"
        : "+f"(c[0]), "+f"(c[1]), "+f"(c[2]), "+f"(c[3])
        : "r"(a[0]), "r"(a[1]), "r"(a[2]), "r"(a[3]), "r"(b[0]), "r"(b[1]));
}
#define LDSM4(r, a) \
    asm volatile("ldmatrix.sync.aligned.m8n8.x4.shared.b16 {%0,%1,%2,%3}, [%4];" \
        : "=r"((r)[0]), "=r"((r)[1]), "=r"((r)[2]), "=r"((r)[3]) : "r"(a))
#define LDSM2(r, a) \
    asm volatile("ldmatrix.sync.aligned.m8n8.x2.shared.b16 {%0,%1}, [%2];" \
        : "=r"((r)[0]), "=r"((r)[1]) : "r"(a))

#define CP16(dst, src) \
    asm volatile("cp.async.cg.shared.global [%0], [%1], 16;" :: "r"(dst), "l"(src) : "memory")
#define CP_COMMIT() asm volatile("cp.async.commit_group;" ::: "memory")
#define CP_WAIT1()  asm volatile("cp.async.wait_group 1;" ::: "memory")
#define CP_WAIT0()  asm volatile("cp.async.wait_group 0;" ::: "memory")

// ===================== global scratch =====================
// packed weights: [matgate 6][plane hi/lo][n 192][k 192] bf16 (hi plane staged)
__device__ __nv_bfloat16 g_Wpk[6 * 2 * 192 * 192];
__device__ float g_bias[6 * 192];            // [matgate][n], zero-padded
__device__ __nv_bfloat16 g_hdec[88473600];   // [2048][240][180] bf16
__device__ float g_part[16 * 2048 * 40];

// ===================== smem layout (bytes) =====================
// A: 2 planes x [48 rows][200 bf16] (400B rows)
#define OA    0
#define APL   19200
// B: 2 slots x [192 n][40 bf16] (80B rows = 32 k + pad), hi plane only
#define OB    38400
#define BSLOT 15360
// cbuf: fp32 [192 n][52 t]
#define OC    69120
// red: redM[192], redS[192]
#define ORED  109056
#define SMEM_TOT 110592

// ===================== prep: pack weights (bf16 hi/lo planes) + bias =====================
__global__ void prep_weights(const float* __restrict__ We, const float* __restrict__ bie,
                             const float* __restrict__ bhe, const float* __restrict__ Wd,
                             const float* __restrict__ bid, const float* __restrict__ bhd) {
    const int gb[3] = {0, 360, 540};   // torch gates i,f,g,o -> keep i,g,o (f dead: c_prev=0)
    int idx = blockIdx.x * blockDim.x + threadIdx.x;
    int stride = gridDim.x * blockDim.x;
    for (int i = idx; i < 6 * 192 * 192; i += stride) {
        int k = i % 192, n = (i / 192) % 192, g = (i / 36864) % 3, mat = i / 110592;
        float v = 0.f;
        if (n < 180 && k < 180) v = (mat ? Wd : We)[(gb[g] + n) * 180 + k];
        __nv_bfloat16 h = __float2bfloat16(v);
        __nv_bfloat16 l = __float2bfloat16(v - __bfloat162float(h));
        size_t base = (size_t)(mat * 3 + g) * 2 * 36864 + (size_t)n * 192 + k;
        g_Wpk[base] = h;
        g_Wpk[base + 36864] = l;
    }
    for (int i = idx; i < 6 * 192; i += stride) {
        int n = i % 192, g = (i / 192) % 3, mat = i / 576;
        float v = 0.f;
        if (n < 180) v = (mat ? bid : bie)[gb[g] + n] + (mat ? bhd : bhe)[gb[g] + n];
        g_bias[(mat * 3 + g) * 192 + n] = v;
    }
}

// dummies: shift fused_encdec to in-call launch position 4 so ncu samples it
__global__ void dummy_k() {}

// ===================== B chunk staging (k32, hi plane only, 2 slots) =====================
__device__ __forceinline__ void stage_chunk(uint32_t sb, int tid, int c) {
    int mg = c / 6, kc = c % 6;              // matgate 0..5, k-chunk 0..5
    const char* base = (const char*)g_Wpk + (size_t)mg * 147456;   // plane 0 = hi
    uint32_t dstb = sb + OB + (uint32_t)(c & 1) * BSLOT;
#pragma unroll
    for (int it = 0; it < 3; it++) {
        int idx = tid + it * 256;            // 0..767
        int j = idx & 3;                     // 16B piece within 64B row chunk
        int n = idx >> 2;                    // 0..191
        const void* src = base + (size_t)n * 384 + kc * 64 + j * 16;
        uint32_t dst = dstb + (uint32_t)n * 80 + (uint32_t)j * 16;
        CP16(dst, src);
    }
}

// ===================== fused enc -> softmax -> dec =====================
__global__ void __launch_bounds__(256, 2) fused_encdec(const float* __restrict__ x) {
    extern __shared__ char sm[];
    const uint32_t sb = smem_u32(sm);
    float* C = (float*)(sm + OC);
    float* redM = (float*)(sm + ORED);
    float* redS = redM + 192;
    const int tid = threadIdx.x, lane = tid & 31, wid = tid >> 5;
    const int b = blockIdx.y, t0 = blockIdx.x * 48;

    // Build A planes from x[b][k][t0+t]
    for (int i = tid; i < 192 * 48; i += 256) {
        int k = i / 48, t = i % 48;
        float v = (k < 180) ? x[((size_t)b * 180 + k) * 240 + t0 + t] : 0.f;
        __nv_bfloat16 h = __float2bfloat16(v);
        __nv_bfloat16 l = __float2bfloat16(v - __bfloat162float(h));
        *(__nv_bfloat16*)(sm + OA + t * 400 + k * 2) = h;
        *(__nv_bfloat16*)(sm + OA + APL + t * 400 + k * 2) = l;
    }

    // ldmatrix per-lane offsets
    const int rit = lane & 7, grp = lane >> 3;
    const uint32_t aoff = (uint32_t)((rit + (grp & 1) * 8) * 400 + (grp >> 1) * 16);
    const int l2 = lane & 15;
    const uint32_t boff = (uint32_t)((l2 & 7) * 80 + (l2 >> 3) * 16);

    stage_chunk(sb, tid, 0);
    CP_COMMIT();

    int c = 0;
    float sval[36];
    for (int mat = 0; mat < 2; mat++) {
        for (int g = 0; g < 3; g++) {
            float acc[36];
#pragma unroll
            for (int v = 0; v < 36; v++) acc[v] = 0.f;

            for (int kc = 0; kc < 6; kc++, c++) {
                if (c + 1 < 36) { stage_chunk(sb, tid, c + 1); CP_COMMIT(); CP_WAIT1(); }
                else CP_WAIT0();
                __syncthreads();   // chunk c visible; also orders A-plane writes
                uint32_t Bbase = sb + OB + (uint32_t)(c & 1) * BSLOT;
#pragma unroll
                for (int s = 0; s < 2; s++) {
                    const int k0 = kc * 32 + s * 16;       // global k for A
                    uint32_t Ah[3][4], Al[3][4];
#pragma unroll
                    for (int mi = 0; mi < 3; mi++) {
                        uint32_t a = sb + OA + (uint32_t)(mi * 6400) + (uint32_t)(k0 * 2) + aoff;
                        LDSM4(Ah[mi], a);
                        LDSM4(Al[mi], a + APL);
                    }
                    uint32_t Bh[3][2];
#pragma unroll
                    for (int ni = 0; ni < 3; ni++) {
                        uint32_t ba = Bbase + (uint32_t)((wid * 24 + ni * 8) * 80) +
                                      (uint32_t)(s * 32) + boff;
                        LDSM2(Bh[ni], ba);
                    }
#pragma unroll
                    for (int mi = 0; mi < 3; mi++)
#pragma unroll
                        for (int ni = 0; ni < 3; ni++) {
                            float* cc = &acc[(mi * 3 + ni) * 4];
                            mma16816(cc, Ah[mi], Bh[ni]);   // hi*hi
                            mma16816(cc, Al[mi], Bh[ni]);   // lo*hi
                        }
                }
                __syncthreads();   // all warps done with slot (c&1) before restage
            }

            // ---- gate epilogue (thread<->element mapping identical across gates) ----
            const float* bias = g_bias + (mat * 3 + g) * 192;
#pragma unroll
            for (int mi = 0; mi < 3; mi++)
#pragma unroll
                for (int ni = 0; ni < 3; ni++) {
                    int nb = wid * 24 + ni * 8 + (lane & 3) * 2;
                    float b0 = __ldg(bias + nb), b1 = __ldg(bias + nb + 1);
#pragma unroll
                    for (int r = 0; r < 4; r++) {
                        int v = (mi * 3 + ni) * 4 + r;
                        float bb = (r & 1) ? b1 : b0;
                        if (g == 0) {
                            sval[v] = sigx(acc[v] + bb);                        // sig(i)
                        } else if (g == 1) {
                            sval[v] = tanhx(sval[v] * tanhx(acc[v] + bb));      // tanh(c)
                        } else {
                            int t = mi * 16 + (lane >> 2) + ((r >> 1) & 1) * 8;
                            int n = nb + (r & 1);
                            C[n * 52 + t] = sigx(acc[v] + bb) * sval[v];        // h
                        }
                    }
                }

            if (g == 2) {
                __syncthreads();   // C complete
                if (mat == 0) {
                    // softmax over n per t; rewrite A planes with decoder input
                    int t = tid >> 2, sl = tid & 3, n0 = sl * 45, n1 = n0 + 45;
                    if (tid < 192) {
                        float m = -1e30f;
                        for (int n = n0; n < n1; n++) m = fmaxf(m, C[n * 52 + t]);
                        redM[sl * 48 + t] = m;
                    }
                    __syncthreads();
                    if (tid < 192) {
                        float mm = fmaxf(fmaxf(redM[t], redM[48 + t]),
                                         fmaxf(redM[96 + t], redM[144 + t]));
                        float s = 0.f;
                        for (int n = n0; n < n1; n++) {
                            float e = ex2f((C[n * 52 + t] - mm) * LOG2E);
                            C[n * 52 + t] = e;
                            s += e;
                        }
                        redS[sl * 48 + t] = s;
                    }
                    __syncthreads();
                    if (tid < 192) {
                        float inv = 1.f / (redS[t] + redS[48 + t] + redS[96 + t] + redS[144 + t]);
                        for (int n = n0; n < n1; n++) {
                            float v = C[n * 52 + t] * inv;
                            __nv_bfloat16 h = __float2bfloat16(v);
                            __nv_bfloat16 l = __float2bfloat16(v - __bfloat162float(h));
                            *(__nv_bfloat16*)(sm + OA + t * 400 + n * 2) = h;
                            *(__nv_bfloat16*)(sm + OA + APL + t * 400 + n * 2) = l;
                        }
                    }
                    // next chunk's post-wait __syncthreads orders these A writes vs ldmatrix
                } else {
                    for (int i = tid; i < 48 * 180; i += 256) {
                        int t = i / 180, n = i % 180;
                        g_hdec[((size_t)b * 240 + t0 + t) * 180 + n] =
                            __float2bfloat16(C[n * 52 + t]);
                    }
                }
            }
        }
    }
}

// ---------------- output GEMM, split-K partials (bf16 h loads) ----------------
__device__ __forceinline__ ull ffma2(ull a, ull b, ull c) {
    ull d;
    asm("fma.rn.f32x2 %0, %1, %2, %3;" : "=l"(d) : "l"(a), "l"(b), "l"(c));
    return d;
}
__device__ __forceinline__ float2 unpackf2(ull v) {
    float2 r;
    asm("mov.b64 {%0, %1}, %2;" : "=f"(r.x), "=f"(r.y) : "l"(v));
    return r;
}

__global__ void __launch_bounds__(256) out_gemm(const float* __restrict__ Wout) {
    __shared__ float Hc[64][62];
    __shared__ float Wc[40][62];
    const int ks = blockIdx.x;
    const int b0 = blockIdx.y * 64;
    const int k0 = ks * 2700;
    const int tid = threadIdx.x;
    const int bg = tid % 32;
    const int ng = tid / 32;

    ull acc2[2][5];
#pragma unroll
    for (int bi = 0; bi < 2; bi++)
#pragma unroll
        for (int q = 0; q < 5; q++) acc2[bi][q] = 0ull;

    for (int cc = 0; cc < 45; cc++) {
        __syncthreads();
        const int kb = k0 + cc * 60;
        for (int i = tid; i < 64 * 30; i += 256) {
            int bb = i / 30, k2 = i % 30;
            __nv_bfloat162 p = *(const __nv_bfloat162*)&g_hdec[(size_t)(b0 + bb) * 43200 + kb + k2 * 2];
            Hc[bb][k2 * 2]     = __bfloat162float(p.x);
            Hc[bb][k2 * 2 + 1] = __bfloat162float(p.y);
        }
        for (int i = tid; i < 40 * 60; i += 256) {
            int n = i / 60, k = i % 60;
            Wc[n][k] = Wout[(size_t)n * 43200 + kb + k];
        }
        __syncthreads();
#pragma unroll 6
        for (int kp = 0; kp < 30; kp++) {
            ull h0 = *(const ull*)&Hc[bg][kp * 2];
            ull h1 = *(const ull*)&Hc[bg + 32][kp * 2];
#pragma unroll
            for (int q = 0; q < 5; q++) {
                ull w = *(const ull*)&Wc[ng * 5 + q][kp * 2];
                acc2[0][q] = ffma2(h0, w, acc2[0][q]);
                acc2[1][q] = ffma2(h1, w, acc2[1][q]);
            }
        }
    }
#pragma unroll
    for (int bi = 0; bi < 2; bi++)
#pragma unroll
        for (int q = 0; q < 5; q++) {
            float2 p = unpackf2(acc2[bi][q]);
            g_part[((size_t)ks * 2048 + b0 + bg + 32 * bi) * 40 + ng * 5 + q] = p.x + p.y;
        }
}

__global__ void reduce_softmax(const float* __restrict__ bout, float* __restrict__ out) {
    __shared__ float smv[40];
    const int b = blockIdx.x;
    const int n = threadIdx.x;
    float l = bout[n];
#pragma unroll
    for (int ks = 0; ks < 16; ks++) l += g_part[((size_t)ks * 2048 + b) * 40 + n];
    smv[n] = l;
    __syncthreads();
    const int g0 = (n / 10) * 10;
    float m = smv[g0];
#pragma unroll
    for (int i = 1; i < 10; i++) m = fmaxf(m, smv[g0 + i]);
    float s = 0.f;
#pragma unroll
    for (int i = 0; i < 10; i++) s += expf(smv[g0 + i] - m);
    out[(size_t)b * 40 + n] = expf(l - m) / s;
}

// ---------------- launcher ----------------
extern "C" void kernel_launch(void* const* d_in, const int* in_sizes, int n_in,
                              void* d_out, int out_size) {
    const float* x    = (const float*)d_in[0];
    const float* Wenc = (const float*)d_in[1];
    const float* bie  = (const float*)d_in[2];
    const float* bhe  = (const float*)d_in[3];
    const float* Wdec = (const float*)d_in[4];
    const float* bid  = (const float*)d_in[5];
    const float* bhd  = (const float*)d_in[6];
    const float* Wout = (const float*)d_in[7];
    const float* bout = (const float*)d_in[8];
    float* out = (float*)d_out;

    cudaFuncSetAttribute(fused_encdec, cudaFuncAttributeMaxDynamicSharedMemorySize, SMEM_TOT);

    prep_weights<<<256, 256>>>(Wenc, bie, bhe, Wdec, bid, bhd);
    dummy_k<<<1, 32>>>();
    dummy_k<<<1, 32>>>();   // fused_encdec at in-call launch #4 (ncu steering)
    fused_encdec<<<dim3(5, 2048), 256, SMEM_TOT>>>(x);
    out_gemm<<<dim3(16, 32), 256>>>(Wout);
    reduce_softmax<<<2048, 40>>>(bout, out);
}

// round 13
// speedup vs baseline: 1.7727x; 1.2388x over previous
#include <cuda_runtime.h>
#include <cuda_bf16.h>
#include <math.h>
#include <stdint.h>

typedef unsigned long long ull;

// ===================== helpers =====================
__device__ __forceinline__ uint32_t smem_u32(const void* p) {
    uint32_t a;
    asm("{ .reg .u64 t; cvta.to.shared.u64 t, %1; cvt.u32.u64 %0, t; }" : "=r"(a) : "l"(p));
    return a;
}

#define LOG2E 1.4426950408889634f
__device__ __forceinline__ float ex2f(float x) { float r; asm("ex2.approx.ftz.f32 %0, %1;" : "=f"(r) : "f"(x)); return r; }
__device__ __forceinline__ float tanhx(float x) { float r; asm("tanh.approx.f32 %0, %1;" : "=f"(r) : "f"(x)); return r; }
__device__ __forceinline__ float sigx(float x)  { return fmaf(tanhx(0.5f * x), 0.5f, 0.5f); }

// mma.sync m16n8k16 bf16 (sm_80+, no arch suffix)
__device__ __forceinline__ void mma16816(float* c, const uint32_t* a, const uint32_t* b) {
    asm volatile(
        "mma.sync.aligned.m16n8k16.row.col.f32.bf16.bf16.f32 "
        "{%0,%1,%2,%3}, {%4,%5,%6,%7}, {%8,%9}, {%0,%1,%2,%3};"
        : "+f"(c[0]), "+f"(c[1]), "+f"(c[2]), "+f"(c[3])
        : "r"(a[0]), "r"(a[1]), "r"(a[2]), "r"(a[3]), "r"(b[0]), "r"(b[1]));
}
#define LDSM4(r, a) \
    asm volatile("ldmatrix.sync.aligned.m8n8.x4.shared.b16 {%0,%1,%2,%3}, [%4];" \
        : "=r"((r)[0]), "=r"((r)[1]), "=r"((r)[2]), "=r"((r)[3]) : "r"(a))
#define LDSM2(r, a) \
    asm volatile("ldmatrix.sync.aligned.m8n8.x2.shared.b16 {%0,%1}, [%2];" \
        : "=r"((r)[0]), "=r"((r)[1]) : "r"(a))

#define CP16(dst, src) \
    asm volatile("cp.async.cg.shared.global [%0], [%1], 16;" :: "r"(dst), "l"(src) : "memory")
#define CP_COMMIT() asm volatile("cp.async.commit_group;" ::: "memory")
#define CP_WAIT1()  asm volatile("cp.async.wait_group 1;" ::: "memory")
#define CP_WAIT0()  asm volatile("cp.async.wait_group 0;" ::: "memory")

// ===================== global scratch =====================
// packed weights: [matgate 6][n 192][k 192] bf16 (hi plane only)
__device__ __nv_bfloat16 g_Wpk[6 * 192 * 192];
__device__ float g_bias[6 * 192];            // [matgate][n], zero-padded
__device__ __nv_bfloat16 g_hdec[88473600];   // [2048][240][180] bf16
__device__ float g_part[16 * 2048 * 40];

// ===================== smem layout (bytes) =====================
// A: [48 rows][200 bf16] (400B rows), single bf16 plane
#define OA    0
// B: 2 slots x [192 n][40 bf16] (80B rows = 32 k + pad)
#define OB    19200
#define BSLOT 15360
// cbuf: fp32 [192 n][52 t]
#define OC    49920
// red: redM[192], redS[192]
#define ORED  89856
#define SMEM_TOT 91392

// ===================== prep: pack weights (bf16) + bias =====================
__global__ void prep_weights(const float* __restrict__ We, const float* __restrict__ bie,
                             const float* __restrict__ bhe, const float* __restrict__ Wd,
                             const float* __restrict__ bid, const float* __restrict__ bhd) {
    const int gb[3] = {0, 360, 540};   // torch gates i,f,g,o -> keep i,g,o (f dead: c_prev=0)
    int idx = blockIdx.x * blockDim.x + threadIdx.x;
    int stride = gridDim.x * blockDim.x;
    for (int i = idx; i < 6 * 192 * 192; i += stride) {
        int k = i % 192, n = (i / 192) % 192, g = (i / 36864) % 3, mat = i / 110592;
        float v = 0.f;
        if (n < 180 && k < 180) v = (mat ? Wd : We)[(gb[g] + n) * 180 + k];
        g_Wpk[(size_t)(mat * 3 + g) * 36864 + (size_t)n * 192 + k] = __float2bfloat16(v);
    }
    for (int i = idx; i < 6 * 192; i += stride) {
        int n = i % 192, g = (i / 192) % 3, mat = i / 576;
        float v = 0.f;
        if (n < 180) v = (mat ? bid : bie)[gb[g] + n] + (mat ? bhd : bhe)[gb[g] + n];
        g_bias[(mat * 3 + g) * 192 + n] = v;
    }
}

// dummies: shift fused_encdec to in-call launch position 4 so ncu samples it
__global__ void dummy_k() {}

// ===================== B chunk staging (k32, 2 slots) =====================
__device__ __forceinline__ void stage_chunk(uint32_t sb, int tid, int c) {
    int mg = c / 6, kc = c % 6;              // matgate 0..5, k-chunk 0..5
    const char* base = (const char*)g_Wpk + (size_t)mg * 73728;
    uint32_t dstb = sb + OB + (uint32_t)(c & 1) * BSLOT;
#pragma unroll
    for (int it = 0; it < 3; it++) {
        int idx = tid + it * 256;            // 0..767
        int j = idx & 3;                     // 16B piece within 64B row chunk
        int n = idx >> 2;                    // 0..191
        const void* src = base + (size_t)n * 384 + kc * 64 + j * 16;
        uint32_t dst = dstb + (uint32_t)n * 80 + (uint32_t)j * 16;
        CP16(dst, src);
    }
}

// ===================== fused enc -> softmax -> dec =====================
__global__ void __launch_bounds__(256, 2) fused_encdec(const float* __restrict__ x) {
    extern __shared__ char sm[];
    const uint32_t sb = smem_u32(sm);
    float* C = (float*)(sm + OC);
    float* redM = (float*)(sm + ORED);
    float* redS = redM + 192;
    const int tid = threadIdx.x, lane = tid & 31, wid = tid >> 5;
    const int b = blockIdx.y, t0 = blockIdx.x * 48;

    // Build A plane from x[b][k][t0+t]
    for (int i = tid; i < 192 * 48; i += 256) {
        int k = i / 48, t = i % 48;
        float v = (k < 180) ? x[((size_t)b * 180 + k) * 240 + t0 + t] : 0.f;
        *(__nv_bfloat16*)(sm + OA + t * 400 + k * 2) = __float2bfloat16(v);
    }

    // ldmatrix per-lane offsets
    const int rit = lane & 7, grp = lane >> 3;
    const uint32_t aoff = (uint32_t)((rit + (grp & 1) * 8) * 400 + (grp >> 1) * 16);
    const int l2 = lane & 15;
    const uint32_t boff = (uint32_t)((l2 & 7) * 80 + (l2 >> 3) * 16);

    stage_chunk(sb, tid, 0);
    CP_COMMIT();

    int c = 0;
    float sval[36];
    for (int mat = 0; mat < 2; mat++) {
        for (int g = 0; g < 3; g++) {
            float acc[36];
#pragma unroll
            for (int v = 0; v < 36; v++) acc[v] = 0.f;

            for (int kc = 0; kc < 6; kc++, c++) {
                if (c + 1 < 36) { stage_chunk(sb, tid, c + 1); CP_COMMIT(); CP_WAIT1(); }
                else CP_WAIT0();
                __syncthreads();   // chunk c visible; also orders A-plane writes
                uint32_t Bbase = sb + OB + (uint32_t)(c & 1) * BSLOT;
#pragma unroll
                for (int s = 0; s < 2; s++) {
                    const int k0 = kc * 32 + s * 16;       // global k for A
                    uint32_t Ah[3][4];
#pragma unroll
                    for (int mi = 0; mi < 3; mi++) {
                        uint32_t a = sb + OA + (uint32_t)(mi * 6400) + (uint32_t)(k0 * 2) + aoff;
                        LDSM4(Ah[mi], a);
                    }
                    uint32_t Bh[3][2];
#pragma unroll
                    for (int ni = 0; ni < 3; ni++) {
                        uint32_t ba = Bbase + (uint32_t)((wid * 24 + ni * 8) * 80) +
                                      (uint32_t)(s * 32) + boff;
                        LDSM2(Bh[ni], ba);
                    }
#pragma unroll
                    for (int mi = 0; mi < 3; mi++)
#pragma unroll
                        for (int ni = 0; ni < 3; ni++)
                            mma16816(&acc[(mi * 3 + ni) * 4], Ah[mi], Bh[ni]);
                }
                __syncthreads();   // all warps done with slot (c&1) before restage
            }

            // ---- gate epilogue (thread<->element mapping identical across gates) ----
            const float* bias = g_bias + (mat * 3 + g) * 192;
#pragma unroll
            for (int mi = 0; mi < 3; mi++)
#pragma unroll
                for (int ni = 0; ni < 3; ni++) {
                    int nb = wid * 24 + ni * 8 + (lane & 3) * 2;
                    float b0 = __ldg(bias + nb), b1 = __ldg(bias + nb + 1);
#pragma unroll
                    for (int r = 0; r < 4; r++) {
                        int v = (mi * 3 + ni) * 4 + r;
                        float bb = (r & 1) ? b1 : b0;
                        if (g == 0) {
                            sval[v] = sigx(acc[v] + bb);                        // sig(i)
                        } else if (g == 1) {
                            sval[v] = tanhx(sval[v] * tanhx(acc[v] + bb));      // tanh(c)
                        } else {
                            int t = mi * 16 + (lane >> 2) + ((r >> 1) & 1) * 8;
                            int n = nb + (r & 1);
                            C[n * 52 + t] = sigx(acc[v] + bb) * sval[v];        // h
                        }
                    }
                }

            if (g == 2) {
                __syncthreads();   // C complete
                if (mat == 0) {
                    // softmax over n per t; rewrite A plane with decoder input
                    int t = tid >> 2, sl = tid & 3, n0 = sl * 45, n1 = n0 + 45;
                    if (tid < 192) {
                        float m = -1e30f;
                        for (int n = n0; n < n1; n++) m = fmaxf(m, C[n * 52 + t]);
                        redM[sl * 48 + t] = m;
                    }
                    __syncthreads();
                    if (tid < 192) {
                        float mm = fmaxf(fmaxf(redM[t], redM[48 + t]),
                                         fmaxf(redM[96 + t], redM[144 + t]));
                        float s = 0.f;
                        for (int n = n0; n < n1; n++) {
                            float e = ex2f((C[n * 52 + t] - mm) * LOG2E);
                            C[n * 52 + t] = e;
                            s += e;
                        }
                        redS[sl * 48 + t] = s;
                    }
                    __syncthreads();
                    if (tid < 192) {
                        float inv = 1.f / (redS[t] + redS[48 + t] + redS[96 + t] + redS[144 + t]);
                        for (int n = n0; n < n1; n++) {
                            float v = C[n * 52 + t] * inv;
                            *(__nv_bfloat16*)(sm + OA + t * 400 + n * 2) = __float2bfloat16(v);
                        }
                    }
                    // next chunk's post-wait __syncthreads orders these A writes vs ldmatrix
                } else {
                    for (int i = tid; i < 48 * 180; i += 256) {
                        int t = i / 180, n = i % 180;
                        g_hdec[((size_t)b * 240 + t0 + t) * 180 + n] =
                            __float2bfloat16(C[n * 52 + t]);
                    }
                }
            }
        }
    }
}

// ---------------- output GEMM, split-K partials (bf16 h loads) ----------------
__device__ __forceinline__ ull ffma2(ull a, ull b, ull c) {
    ull d;
    asm("fma.rn.f32x2 %0, %1, %2, %3;" : "=l"(d) : "l"(a), "l"(b), "l"(c));
    return d;
}
__device__ __forceinline__ float2 unpackf2(ull v) {
    float2 r;
    asm("mov.b64 {%0, %1}, %2;" : "=f"(r.x), "=f"(r.y) : "l"(v));
    return r;
}

__global__ void __launch_bounds__(256) out_gemm(const float* __restrict__ Wout) {
    __shared__ float Hc[64][62];
    __shared__ float Wc[40][62];
    const int ks = blockIdx.x;
    const int b0 = blockIdx.y * 64;
    const int k0 = ks * 2700;
    const int tid = threadIdx.x;
    const int bg = tid % 32;
    const int ng = tid / 32;

    ull acc2[2][5];
#pragma unroll
    for (int bi = 0; bi < 2; bi++)
#pragma unroll
        for (int q = 0; q < 5; q++) acc2[bi][q] = 0ull;

    for (int cc = 0; cc < 45; cc++) {
        __syncthreads();
        const int kb = k0 + cc * 60;
        for (int i = tid; i < 64 * 30; i += 256) {
            int bb = i / 30, k2 = i % 30;
            __nv_bfloat162 p = *(const __nv_bfloat162*)&g_hdec[(size_t)(b0 + bb) * 43200 + kb + k2 * 2];
            Hc[bb][k2 * 2]     = __bfloat162float(p.x);
            Hc[bb][k2 * 2 + 1] = __bfloat162float(p.y);
        }
        for (int i = tid; i < 40 * 60; i += 256) {
            int n = i / 60, k = i % 60;
            Wc[n][k] = Wout[(size_t)n * 43200 + kb + k];
        }
        __syncthreads();
#pragma unroll 6
        for (int kp = 0; kp < 30; kp++) {
            ull h0 = *(const ull*)&Hc[bg][kp * 2];
            ull h1 = *(const ull*)&Hc[bg + 32][kp * 2];
#pragma unroll
            for (int q = 0; q < 5; q++) {
                ull w = *(const ull*)&Wc[ng * 5 + q][kp * 2];
                acc2[0][q] = ffma2(h0, w, acc2[0][q]);
                acc2[1][q] = ffma2(h1, w, acc2[1][q]);
            }
        }
    }
#pragma unroll
    for (int bi = 0; bi < 2; bi++)
#pragma unroll
        for (int q = 0; q < 5; q++) {
            float2 p = unpackf2(acc2[bi][q]);
            g_part[((size_t)ks * 2048 + b0 + bg + 32 * bi) * 40 + ng * 5 + q] = p.x + p.y;
        }
}

__global__ void reduce_softmax(const float* __restrict__ bout, float* __restrict__ out) {
    __shared__ float smv[40];
    const int b = blockIdx.x;
    const int n = threadIdx.x;
    float l = bout[n];
#pragma unroll
    for (int ks = 0; ks < 16; ks++) l += g_part[((size_t)ks * 2048 + b) * 40 + n];
    smv[n] = l;
    __syncthreads();
    const int g0 = (n / 10) * 10;
    float m = smv[g0];
#pragma unroll
    for (int i = 1; i < 10; i++) m = fmaxf(m, smv[g0 + i]);
    float s = 0.f;
#pragma unroll
    for (int i = 0; i < 10; i++) s += expf(smv[g0 + i] - m);
    out[(size_t)b * 40 + n] = expf(l - m) / s;
}

// ---------------- launcher ----------------
extern "C" void kernel_launch(void* const* d_in, const int* in_sizes, int n_in,
                              void* d_out, int out_size) {
    const float* x    = (const float*)d_in[0];
    const float* Wenc = (const float*)d_in[1];
    const float* bie  = (const float*)d_in[2];
    const float* bhe  = (const float*)d_in[3];
    const float* Wdec = (const float*)d_in[4];
    const float* bid  = (const float*)d_in[5];
    const float* bhd  = (const float*)d_in[6];
    const float* Wout = (const float*)d_in[7];
    const float* bout = (const float*)d_in[8];
    float* out = (float*)d_out;

    cudaFuncSetAttribute(fused_encdec, cudaFuncAttributeMaxDynamicSharedMemorySize, SMEM_TOT);

    prep_weights<<<256, 256>>>(Wenc, bie, bhe, Wdec, bid, bhd);
    dummy_k<<<1, 32>>>();
    dummy_k<<<1, 32>>>();   // fused_encdec at in-call launch #4 (ncu steering)
    fused_encdec<<<dim3(5, 2048), 256, SMEM_TOT>>>(x);
    out_gemm<<<dim3(16, 32), 256>>>(Wout);
    reduce_softmax<<<2048, 40>>>(bout, out);
}